// round 2
// baseline (speedup 1.0000x reference)
#include <cuda_runtime.h>
#include <cuda_bf16.h>

// Problem shapes (fixed by the reference)
#define BATCH 8
#define CCH   512          // channels
#define NSP   4096         // H*W = 64*64

// Scratch: q,k,v [3][B][C][N] and attn [B][C][C]
__device__ float g_qkv[(size_t)3 * BATCH * CCH * NSP];      // 192 MB
__device__ float g_attn[(size_t)BATCH * CCH * CCH];         // 8 MB

// ---------------- Tiled SGEMM core ----------------
// C_tile[BM x BN] = A[M,K] * op(B), A row-major ldA, B row-major ldB.
// NT=false: B is [K,N]  (use B[k][n])
// NT=true : B is [N,K]  (use B[n][k], i.e. A*B^T)
#define BM 128
#define BN 128
#define BK 16

template<bool NT>
__device__ __forceinline__ void gemm_block(const float* __restrict__ A,
                                           const float* __restrict__ B,
                                           int K, int ldA, int ldB,
                                           float acc[8][8]) {
    __shared__ float As[BK][BM + 4];
    __shared__ float Bs[BK][BN + 4];

    const int tid = threadIdx.x;
    const int tx  = tid & 15;        // 0..15 -> col group
    const int ty  = tid >> 4;        // 0..15 -> row group
    const int brow = blockIdx.y * BM;
    const int bcol = blockIdx.x * BN;

    for (int k0 = 0; k0 < K; k0 += BK) {
        // ---- load A tile (BM x BK), transpose into As[k][m] ----
        #pragma unroll
        for (int i = 0; i < 2; i++) {
            int idx = tid + i * 256;
            int m   = idx >> 2;             // 0..127
            int kc  = (idx & 3) << 2;       // 0,4,8,12
            float4 v = *(const float4*)(A + (size_t)(brow + m) * ldA + k0 + kc);
            As[kc + 0][m] = v.x;
            As[kc + 1][m] = v.y;
            As[kc + 2][m] = v.z;
            As[kc + 3][m] = v.w;
        }
        // ---- load B tile ----
        if (NT) {
            // B is [N,K] row-major: load row n, cols k0..k0+15, transpose
            #pragma unroll
            for (int i = 0; i < 2; i++) {
                int idx = tid + i * 256;
                int n   = idx >> 2;
                int kc  = (idx & 3) << 2;
                float4 v = *(const float4*)(B + (size_t)(bcol + n) * ldB + k0 + kc);
                Bs[kc + 0][n] = v.x;
                Bs[kc + 1][n] = v.y;
                Bs[kc + 2][n] = v.z;
                Bs[kc + 3][n] = v.w;
            }
        } else {
            // B is [K,N] row-major: direct vector copy
            #pragma unroll
            for (int i = 0; i < 2; i++) {
                int idx = tid + i * 256;
                int kk  = idx >> 5;             // 0..15
                int nc  = (idx & 31) << 2;      // 0..124
                *(float4*)&Bs[kk][nc] =
                    *(const float4*)(B + (size_t)(k0 + kk) * ldB + bcol + nc);
            }
        }
        __syncthreads();

        // ---- compute ----
        #pragma unroll
        for (int kk = 0; kk < BK; kk++) {
            float ar[8], br[8];
            #pragma unroll
            for (int i = 0; i < 8; i++) ar[i] = As[kk][ty * 8 + i];
            #pragma unroll
            for (int j = 0; j < 8; j++) br[j] = Bs[kk][tx * 8 + j];
            #pragma unroll
            for (int i = 0; i < 8; i++)
                #pragma unroll
                for (int j = 0; j < 8; j++)
                    acc[i][j] += ar[i] * br[j];
        }
        __syncthreads();
    }
}

// ---------------- Kernel 1: QKV projections ----------------
// grid: (NSP/BN=32, CCH/BM=4, BATCH*3)
__global__ __launch_bounds__(256) void qkv_kernel(
    const float* __restrict__ x,
    const float* __restrict__ wq, const float* __restrict__ bq,
    const float* __restrict__ wk, const float* __restrict__ bk,
    const float* __restrict__ wv, const float* __restrict__ bv)
{
    const int z     = blockIdx.z;
    const int batch = z / 3;
    const int which = z % 3;
    const float* w  = (which == 0) ? wq : (which == 1) ? wk : wv;
    const float* b  = (which == 0) ? bq : (which == 1) ? bk : bv;
    const float* Bm = x + (size_t)batch * CCH * NSP;

    float acc[8][8];
    #pragma unroll
    for (int i = 0; i < 8; i++)
        #pragma unroll
        for (int j = 0; j < 8; j++) acc[i][j] = 0.f;

    gemm_block<false>(w, Bm, CCH, CCH, NSP, acc);

    float* out = g_qkv + ((size_t)which * BATCH + batch) * CCH * NSP;
    const int tid = threadIdx.x;
    const int tx = tid & 15, ty = tid >> 4;
    const int row0 = blockIdx.y * BM + ty * 8;
    const int col0 = blockIdx.x * BN + tx * 8;
    #pragma unroll
    for (int i = 0; i < 8; i++) {
        float bi = b[row0 + i];
        float4 v0 = make_float4(acc[i][0] + bi, acc[i][1] + bi, acc[i][2] + bi, acc[i][3] + bi);
        float4 v1 = make_float4(acc[i][4] + bi, acc[i][5] + bi, acc[i][6] + bi, acc[i][7] + bi);
        float* p = out + (size_t)(row0 + i) * NSP + col0;
        *(float4*)(p)     = v0;
        *(float4*)(p + 4) = v1;
    }
}

// ---------------- Kernel 2: attn = q @ k^T ----------------
// grid: (CCH/BN=4, CCH/BM=4, BATCH)
__global__ __launch_bounds__(256) void attn_kernel()
{
    const int batch = blockIdx.z;
    const float* q = g_qkv + ((size_t)0 * BATCH + batch) * CCH * NSP;
    const float* k = g_qkv + ((size_t)1 * BATCH + batch) * CCH * NSP;

    float acc[8][8];
    #pragma unroll
    for (int i = 0; i < 8; i++)
        #pragma unroll
        for (int j = 0; j < 8; j++) acc[i][j] = 0.f;

    gemm_block<true>(q, k, NSP, NSP, NSP, acc);

    float* out = g_attn + (size_t)batch * CCH * CCH;
    const int tid = threadIdx.x;
    const int tx = tid & 15, ty = tid >> 4;
    const int row0 = blockIdx.y * BM + ty * 8;
    const int col0 = blockIdx.x * BN + tx * 8;
    #pragma unroll
    for (int i = 0; i < 8; i++) {
        float* p = out + (size_t)(row0 + i) * CCH + col0;
        *(float4*)(p)     = make_float4(acc[i][0], acc[i][1], acc[i][2], acc[i][3]);
        *(float4*)(p + 4) = make_float4(acc[i][4], acc[i][5], acc[i][6], acc[i][7]);
    }
}

// ---------------- Kernel 3: row softmax over g_attn ----------------
// grid: BATCH*CCH blocks, 256 threads; each thread handles 2 of 512 elems
__global__ __launch_bounds__(256) void softmax_kernel()
{
    const size_t row = blockIdx.x;
    float* p = g_attn + row * CCH;
    const int tid = threadIdx.x;

    float v0 = p[tid];
    float v1 = p[tid + 256];

    __shared__ float red[8];
    // max reduce
    float m = fmaxf(v0, v1);
    #pragma unroll
    for (int o = 16; o > 0; o >>= 1) m = fmaxf(m, __shfl_xor_sync(0xffffffffu, m, o));
    if ((tid & 31) == 0) red[tid >> 5] = m;
    __syncthreads();
    if (tid < 8) {
        float t = red[tid];
        #pragma unroll
        for (int o = 4; o > 0; o >>= 1) t = fmaxf(t, __shfl_xor_sync(0xffu, t, o));
        red[tid] = t;
    }
    __syncthreads();
    m = red[0];

    float e0 = expf(v0 - m);
    float e1 = expf(v1 - m);

    __shared__ float red2[8];
    float s = e0 + e1;
    #pragma unroll
    for (int o = 16; o > 0; o >>= 1) s += __shfl_xor_sync(0xffffffffu, s, o);
    if ((tid & 31) == 0) red2[tid >> 5] = s;
    __syncthreads();
    if (tid < 8) {
        float t = red2[tid];
        #pragma unroll
        for (int o = 4; o > 0; o >>= 1) t += __shfl_xor_sync(0xffu, t, o);
        red2[tid] = t;
    }
    __syncthreads();
    s = red2[0];

    float inv = 1.0f / s;
    p[tid]       = e0 * inv;
    p[tid + 256] = e1 * inv;
}

// ---------------- Kernel 4: out = attn @ v + x ----------------
// grid: (NSP/BN=32, CCH/BM=4, BATCH)
__global__ __launch_bounds__(256) void out_kernel(
    const float* __restrict__ x, float* __restrict__ out)
{
    const int batch = blockIdx.z;
    const float* A  = g_attn + (size_t)batch * CCH * CCH;
    const float* v  = g_qkv + ((size_t)2 * BATCH + batch) * CCH * NSP;
    const float* xb = x + (size_t)batch * CCH * NSP;
    float* ob       = out + (size_t)batch * CCH * NSP;

    float acc[8][8];
    #pragma unroll
    for (int i = 0; i < 8; i++)
        #pragma unroll
        for (int j = 0; j < 8; j++) acc[i][j] = 0.f;

    gemm_block<false>(A, v, CCH, CCH, NSP, acc);

    const int tid = threadIdx.x;
    const int tx = tid & 15, ty = tid >> 4;
    const int row0 = blockIdx.y * BM + ty * 8;
    const int col0 = blockIdx.x * BN + tx * 8;
    #pragma unroll
    for (int i = 0; i < 8; i++) {
        const float* xp = xb + (size_t)(row0 + i) * NSP + col0;
        float4 x0 = *(const float4*)(xp);
        float4 x1 = *(const float4*)(xp + 4);
        float* p = ob + (size_t)(row0 + i) * NSP + col0;
        *(float4*)(p) = make_float4(acc[i][0] + x0.x, acc[i][1] + x0.y,
                                    acc[i][2] + x0.z, acc[i][3] + x0.w);
        *(float4*)(p + 4) = make_float4(acc[i][4] + x1.x, acc[i][5] + x1.y,
                                        acc[i][6] + x1.z, acc[i][7] + x1.w);
    }
}

// ---------------- launch ----------------
extern "C" void kernel_launch(void* const* d_in, const int* in_sizes, int n_in,
                              void* d_out, int out_size) {
    const float* x  = (const float*)d_in[0];
    const float* wq = (const float*)d_in[1];
    const float* bq = (const float*)d_in[2];
    const float* wk = (const float*)d_in[3];
    const float* bk = (const float*)d_in[4];
    const float* wv = (const float*)d_in[5];
    const float* bv = (const float*)d_in[6];
    float* out = (float*)d_out;

    dim3 blk(256);

    dim3 g1(NSP / BN, CCH / BM, BATCH * 3);
    qkv_kernel<<<g1, blk>>>(x, wq, bq, wk, bk, wv, bv);

    dim3 g2(CCH / BN, CCH / BM, BATCH);
    attn_kernel<<<g2, blk>>>();

    softmax_kernel<<<BATCH * CCH, blk>>>();

    dim3 g4(NSP / BN, CCH / BM, BATCH);
    out_kernel<<<g4, blk>>>(x, out);
}

// round 4
// speedup vs baseline: 2.9669x; 2.9669x over previous
#include <cuda_runtime.h>
#include <cuda_bf16.h>
#include <cstdint>

#define BATCH 8
#define CH    512
#define NSP   4096

// ---------------- global scratch, all hi/lo K-packed ----------------
// packed row layout: [k/64 chunk][hi 64 | lo 64] bf16  (128 elems = 256B per chunk)
__device__ __align__(16) __nv_bfloat16 g_w   [(size_t)3 * CH * (CH * 2)];        // rows=c, K=c (3 MB)
__device__ __align__(16) __nv_bfloat16 g_xt  [(size_t)BATCH * NSP * (CH * 2)];   // rows=n, K=c (64+ MB)
__device__ __align__(16) __nv_bfloat16 g_q   [(size_t)BATCH * CH * (NSP * 2)];   // rows=c, K=n
__device__ __align__(16) __nv_bfloat16 g_k   [(size_t)BATCH * CH * (NSP * 2)];   // rows=c, K=n
__device__ __align__(16) __nv_bfloat16 g_vt  [(size_t)BATCH * NSP * (CH * 2)];   // rows=n, K=c
__device__ __align__(16) __nv_bfloat16 g_attn_p[(size_t)BATCH * CH * (CH * 2)];  // rows=c, K=d
__device__ __align__(16) float         g_attn_raw[(size_t)BATCH * CH * CH];

// ---------------- low-level helpers ----------------
__device__ __forceinline__ uint32_t smem_u32(const void* p) {
    uint32_t a;
    asm("{ .reg .u64 t; cvta.to.shared.u64 t, %1; cvt.u32.u64 %0, t; }" : "=r"(a) : "l"(p));
    return a;
}
__device__ __forceinline__ void cp16(uint32_t s, const void* g) {
    asm volatile("cp.async.cg.shared.global [%0], [%1], 16;" :: "r"(s), "l"(g));
}
__device__ __forceinline__ void ldsm4(uint32_t* r, uint32_t addr) {
    asm volatile("ldmatrix.sync.aligned.m8n8.x4.shared.b16 {%0,%1,%2,%3}, [%4];"
                 : "=r"(r[0]), "=r"(r[1]), "=r"(r[2]), "=r"(r[3]) : "r"(addr));
}
__device__ __forceinline__ void mma16816(float* d, const uint32_t* a, const uint32_t* b) {
    asm volatile("mma.sync.aligned.m16n8k16.row.col.f32.bf16.bf16.f32 "
                 "{%0,%1,%2,%3}, {%4,%5,%6,%7}, {%8,%9}, {%0,%1,%2,%3};"
                 : "+f"(d[0]), "+f"(d[1]), "+f"(d[2]), "+f"(d[3])
                 : "r"(a[0]), "r"(a[1]), "r"(a[2]), "r"(a[3]), "r"(b[0]), "r"(b[1]));
}
__device__ __forceinline__ void split2(float f, __nv_bfloat16& h, __nv_bfloat16& l) {
    h = __float2bfloat16(f);
    l = __float2bfloat16(f - __bfloat162float(h));
}

// Load one 128-row x 256B chunk tile into smem with XOR-8 swizzle on 16B units.
__device__ __forceinline__ void load_tile(uint32_t sdst, const __nv_bfloat16* gsrc,
                                          size_t rowlen, int tid) {
    #pragma unroll
    for (int i = 0; i < 8; i++) {
        int idx = tid + i * 256;
        int r = idx >> 4, u = idx & 15;
        cp16(sdst + r * 256 + ((u ^ (r & 7)) * 16),
             gsrc + (size_t)r * rowlen + u * 8);
    }
}

// ---------------- GEMM core: C[128][128] += A[128,K] * B[128,K]^T ----------------
// A,B rows are K-major hi/lo packed. nch = K/64. TERMS: 3 = hh+hl+lh, 4 adds ll.
template<int TERMS>
__device__ __forceinline__ void gemm_core(const __nv_bfloat16* __restrict__ Ag,
                                          const __nv_bfloat16* __restrict__ Bg,
                                          int nch, size_t lda, size_t ldb,
                                          float (&acc)[4][4][4]) {
    extern __shared__ char smem[];
    const uint32_t sb = smem_u32(smem);
    const int tid = threadIdx.x;
    const int lane = tid & 31, w = tid >> 5;
    const int wm = (w >> 2) * 64, wn = (w & 3) * 32;

    #pragma unroll
    for (int i = 0; i < 4; i++)
        #pragma unroll
        for (int j = 0; j < 4; j++)
            #pragma unroll
            for (int r = 0; r < 4; r++) acc[i][j][r] = 0.f;

    // smem: [stage][A 32KB | B 32KB]
    load_tile(sb,          Ag, lda, tid);
    load_tile(sb + 32768,  Bg, ldb, tid);
    asm volatile("cp.async.commit_group;" ::: "memory");
    if (nch > 1) {
        load_tile(sb + 65536, Ag + 128, lda, tid);
        load_tile(sb + 98304, Bg + 128, ldb, tid);
    }
    asm volatile("cp.async.commit_group;" ::: "memory");

    for (int ch = 0; ch < nch; ch++) {
        asm volatile("cp.async.wait_group 1;" ::: "memory");
        __syncthreads();
        const uint32_t s_a = sb + (ch & 1) * 65536;
        const uint32_t s_b = s_a + 32768;

        #pragma unroll
        for (int ks = 0; ks < 4; ks++) {
            uint32_t ah[4][4], al[4][4], bh[2][4], bl[2][4];
            #pragma unroll
            for (int i = 0; i < 4; i++) {
                int r = wm + 16 * i + (lane & 7) + ((lane >> 3) & 1) * 8;
                int u = 2 * ks + ((lane >> 4) & 1);
                ldsm4(ah[i], s_a + r * 256 + ((u       ^ (r & 7)) * 16));
                ldsm4(al[i], s_a + r * 256 + (((u + 8) ^ (r & 7)) * 16));
            }
            #pragma unroll
            for (int jj = 0; jj < 2; jj++) {
                int r = wn + 16 * jj + (lane & 7) + ((lane >> 4) & 1) * 8;
                int u = 2 * ks + ((lane >> 3) & 1);
                ldsm4(bh[jj], s_b + r * 256 + ((u       ^ (r & 7)) * 16));
                ldsm4(bl[jj], s_b + r * 256 + (((u + 8) ^ (r & 7)) * 16));
            }
            #pragma unroll
            for (int i = 0; i < 4; i++)
                #pragma unroll
                for (int j = 0; j < 4; j++)
                    mma16816(acc[i][j], ah[i], &bh[j >> 1][(j & 1) * 2]);
            #pragma unroll
            for (int i = 0; i < 4; i++)
                #pragma unroll
                for (int j = 0; j < 4; j++)
                    mma16816(acc[i][j], ah[i], &bl[j >> 1][(j & 1) * 2]);
            #pragma unroll
            for (int i = 0; i < 4; i++)
                #pragma unroll
                for (int j = 0; j < 4; j++)
                    mma16816(acc[i][j], al[i], &bh[j >> 1][(j & 1) * 2]);
            if (TERMS == 4) {
                #pragma unroll
                for (int i = 0; i < 4; i++)
                    #pragma unroll
                    for (int j = 0; j < 4; j++)
                        mma16816(acc[i][j], al[i], &bl[j >> 1][(j & 1) * 2]);
            }
        }
        __syncthreads();
        if (ch + 2 < nch) {
            const uint32_t d_a = sb + (ch & 1) * 65536;
            load_tile(d_a,         Ag + (size_t)(ch + 2) * 128, lda, tid);
            load_tile(d_a + 32768, Bg + (size_t)(ch + 2) * 128, ldb, tid);
        }
        asm volatile("cp.async.commit_group;" ::: "memory");
    }
    asm volatile("cp.async.wait_group 0;" ::: "memory");
    __syncthreads();
}

#define PITCH 132
__device__ __forceinline__ void store_acc(float* smemf, const float (&acc)[4][4][4],
                                          int lane, int wm, int wn, bool transpose) {
    #pragma unroll
    for (int i = 0; i < 4; i++)
        #pragma unroll
        for (int j = 0; j < 4; j++)
            #pragma unroll
            for (int r = 0; r < 4; r++) {
                int m = wm + 16 * i + (lane >> 2) + 8 * (r >> 1);
                int n = wn + 8 * j + 2 * (lane & 3) + (r & 1);
                if (transpose) smemf[n * PITCH + m] = acc[i][j][r];
                else           smemf[m * PITCH + n] = acc[i][j][r];
            }
}

// ---------------- kernel 1: QKV projections ----------------
// grid (NSP/128=32, CH/128=4, BATCH*3)
__global__ __launch_bounds__(256, 1) void qkv_gemm(
    const float* __restrict__ bq, const float* __restrict__ bk, const float* __restrict__ bv)
{
    const int z = blockIdx.z;
    const int batch = z / 3, which = z % 3;
    const int c0 = blockIdx.y * 128, n0 = blockIdx.x * 128;

    const __nv_bfloat16* Ag = g_w + (size_t)which * CH * (CH * 2) + (size_t)c0 * (CH * 2);
    const __nv_bfloat16* Bg = g_xt + ((size_t)batch * NSP + n0) * (CH * 2);

    float acc[4][4][4];
    gemm_core<3>(Ag, Bg, CH / 64, CH * 2, CH * 2, acc);

    extern __shared__ char smem[];
    float* smemf = (float*)smem;
    const int tid = threadIdx.x, lane = tid & 31, w = tid >> 5;
    const int wm = (w >> 2) * 64, wn = (w & 3) * 32;

    store_acc(smemf, acc, lane, wm, wn, which == 2);   // v stored transposed (rows=n)
    __syncthreads();

    const float* bias = (which == 0) ? bq : (which == 1) ? bk : bv;
    const int chunk = lane >> 4, part = (lane >> 3) & 1, sub = lane & 7;

    if (which < 2) {
        __nv_bfloat16* dst = ((which == 0) ? g_q : g_k)
                             + ((size_t)batch * CH + c0) * (NSP * 2) + (size_t)n0 * 2;
        #pragma unroll 4
        for (int rr = 0; rr < 16; rr++) {
            int row = w * 16 + rr;
            float bvv = bias[c0 + row];
            const float* src = smemf + row * PITCH + chunk * 64 + sub * 8;
            float4 f0 = *(const float4*)src, f1 = *(const float4*)(src + 4);
            float vv[8] = {f0.x + bvv, f0.y + bvv, f0.z + bvv, f0.w + bvv,
                           f1.x + bvv, f1.y + bvv, f1.z + bvv, f1.w + bvv};
            unsigned short o8[8];
            #pragma unroll
            for (int e = 0; e < 8; e++) {
                __nv_bfloat16 h = __float2bfloat16(vv[e]);
                if (part) h = __float2bfloat16(vv[e] - __bfloat162float(h));
                o8[e] = __bfloat16_as_ushort(h);
            }
            *(uint4*)(dst + (size_t)row * (NSP * 2) + chunk * 128 + part * 64 + sub * 8)
                = *(const uint4*)o8;
        }
    } else {
        __nv_bfloat16* dst = g_vt + ((size_t)batch * NSP + n0) * (CH * 2) + (size_t)c0 * 2;
        #pragma unroll 4
        for (int rr = 0; rr < 16; rr++) {
            int row = w * 16 + rr;                         // local n
            const float* src = smemf + row * PITCH + chunk * 64 + sub * 8;
            const float* bp  = bias + c0 + chunk * 64 + sub * 8;
            float4 f0 = *(const float4*)src, f1 = *(const float4*)(src + 4);
            float4 b0 = *(const float4*)bp,  b1 = *(const float4*)(bp + 4);
            float vv[8] = {f0.x + b0.x, f0.y + b0.y, f0.z + b0.z, f0.w + b0.w,
                           f1.x + b1.x, f1.y + b1.y, f1.z + b1.z, f1.w + b1.w};
            unsigned short o8[8];
            #pragma unroll
            for (int e = 0; e < 8; e++) {
                __nv_bfloat16 h = __float2bfloat16(vv[e]);
                if (part) h = __float2bfloat16(vv[e] - __bfloat162float(h));
                o8[e] = __bfloat16_as_ushort(h);
            }
            *(uint4*)(dst + (size_t)row * (CH * 2) + chunk * 128 + part * 64 + sub * 8)
                = *(const uint4*)o8;
        }
    }
}

// ---------------- kernel 2: attn = q @ k^T (4-term for accuracy) ----------------
// grid (CH/128=4, CH/128=4, BATCH)
__global__ __launch_bounds__(256, 1) void attn_gemm()
{
    const int batch = blockIdx.z;
    const int c0 = blockIdx.y * 128, d0 = blockIdx.x * 128;

    const __nv_bfloat16* Ag = g_q + ((size_t)batch * CH + c0) * (NSP * 2);
    const __nv_bfloat16* Bg = g_k + ((size_t)batch * CH + d0) * (NSP * 2);

    float acc[4][4][4];
    gemm_core<4>(Ag, Bg, NSP / 64, NSP * 2, NSP * 2, acc);

    extern __shared__ char smem[];
    float* smemf = (float*)smem;
    const int tid = threadIdx.x, lane = tid & 31, w = tid >> 5;
    store_acc(smemf, acc, lane, (w >> 2) * 64, (w & 3) * 32, false);
    __syncthreads();

    #pragma unroll 4
    for (int rr = 0; rr < 16; rr++) {
        int row = w * 16 + rr;
        const float* src = smemf + row * PITCH + 4 * lane;
        *(float4*)(g_attn_raw + ((size_t)batch * CH + c0 + row) * CH + d0 + 4 * lane)
            = *(const float4*)src;
    }
}

// ---------------- kernel 3: softmax + hi/lo pack ----------------
__global__ __launch_bounds__(256) void softmax_kernel()
{
    const size_t row = blockIdx.x;
    const float* p = g_attn_raw + row * CH;
    const int tid = threadIdx.x;

    float v0 = p[tid], v1 = p[tid + 256];

    __shared__ float red[8];
    float m = fmaxf(v0, v1);
    #pragma unroll
    for (int o = 16; o > 0; o >>= 1) m = fmaxf(m, __shfl_xor_sync(0xffffffffu, m, o));
    if ((tid & 31) == 0) red[tid >> 5] = m;
    __syncthreads();
    if (tid < 8) {
        float t = red[tid];
        #pragma unroll
        for (int o = 4; o > 0; o >>= 1) t = fmaxf(t, __shfl_xor_sync(0xffu, t, o));
        red[tid] = t;
    }
    __syncthreads();
    m = red[0];

    float e0 = expf(v0 - m), e1 = expf(v1 - m);

    __shared__ float red2[8];
    float s = e0 + e1;
    #pragma unroll
    for (int o = 16; o > 0; o >>= 1) s += __shfl_xor_sync(0xffffffffu, s, o);
    if ((tid & 31) == 0) red2[tid >> 5] = s;
    __syncthreads();
    if (tid < 8) {
        float t = red2[tid];
        #pragma unroll
        for (int o = 4; o > 0; o >>= 1) t += __shfl_xor_sync(0xffu, t, o);
        red2[tid] = t;
    }
    __syncthreads();
    s = red2[0];

    const float inv = 1.0f / s;
    __nv_bfloat16 h, l;
    __nv_bfloat16* dst = g_attn_p + row * (CH * 2);
    int d = tid;
    split2(e0 * inv, h, l);
    dst[(d >> 6) * 128 + (d & 63)]      = h;
    dst[(d >> 6) * 128 + 64 + (d & 63)] = l;
    d = tid + 256;
    split2(e1 * inv, h, l);
    dst[(d >> 6) * 128 + (d & 63)]      = h;
    dst[(d >> 6) * 128 + 64 + (d & 63)] = l;
}

// ---------------- kernel 4: out = attn @ v + x ----------------
// grid (NSP/128=32, CH/128=4, BATCH)
__global__ __launch_bounds__(256, 1) void out_gemm(
    const float* __restrict__ x, float* __restrict__ out)
{
    const int batch = blockIdx.z;
    const int c0 = blockIdx.y * 128, n0 = blockIdx.x * 128;

    const __nv_bfloat16* Ag = g_attn_p + ((size_t)batch * CH + c0) * (CH * 2);
    const __nv_bfloat16* Bg = g_vt + ((size_t)batch * NSP + n0) * (CH * 2);

    float acc[4][4][4];
    gemm_core<3>(Ag, Bg, CH / 64, CH * 2, CH * 2, acc);

    extern __shared__ char smem[];
    float* smemf = (float*)smem;
    const int tid = threadIdx.x, lane = tid & 31, w = tid >> 5;
    store_acc(smemf, acc, lane, (w >> 2) * 64, (w & 3) * 32, false);
    __syncthreads();

    #pragma unroll 4
    for (int rr = 0; rr < 16; rr++) {
        int row = w * 16 + rr;
        size_t off = ((size_t)batch * CH + c0 + row) * NSP + n0 + 4 * lane;
        float4 a = *(const float4*)(smemf + row * PITCH + 4 * lane);
        float4 xr = *(const float4*)(x + off);
        *(float4*)(out + off) = make_float4(a.x + xr.x, a.y + xr.y, a.z + xr.z, a.w + xr.w);
    }
}

// ---------------- split / pack kernels ----------------
__global__ __launch_bounds__(256) void split_w_kernel(
    const float* __restrict__ wq, const float* __restrict__ wk, const float* __restrict__ wv)
{
    int idx = blockIdx.x * 256 + threadIdx.x;          // 0 .. 3*512*512-1
    int which = idx >> 18;
    int rem = idx & 0x3FFFF;
    int row = rem >> 9, kk = rem & 511;
    const float* wsrc = (which == 0) ? wq : (which == 1) ? wk : wv;
    float f = wsrc[row * CH + kk];
    __nv_bfloat16 h, l; split2(f, h, l);
    __nv_bfloat16* dst = g_w + (size_t)which * CH * (CH * 2) + (size_t)row * (CH * 2)
                         + (kk >> 6) * 128 + (kk & 63);
    dst[0] = h; dst[64] = l;
}

// x[b][c][n] -> xt packed rows n, K=c
__global__ __launch_bounds__(256) void split_xt_kernel(const float* __restrict__ x)
{
    __shared__ float t[32][33];
    const int b = blockIdx.z;
    const int n0 = blockIdx.x * 32, c0 = blockIdx.y * 32;
    const int tx = threadIdx.x, ty = threadIdx.y;      // 32 x 8
    #pragma unroll
    for (int i = 0; i < 4; i++) {
        int c = c0 + ty + i * 8;
        t[ty + i * 8][tx] = x[((size_t)b * CH + c) * NSP + n0 + tx];
    }
    __syncthreads();
    #pragma unroll
    for (int i = 0; i < 4; i++) {
        int nl = ty + i * 8;
        float f = t[tx][nl];
        __nv_bfloat16 h, l; split2(f, h, l);
        int c = c0 + tx;
        __nv_bfloat16* dst = g_xt + ((size_t)b * NSP + n0 + nl) * (CH * 2)
                             + (c >> 6) * 128 + (c & 63);
        dst[0] = h; dst[64] = l;
    }
}

// ---------------- launch ----------------
extern "C" void kernel_launch(void* const* d_in, const int* in_sizes, int n_in,
                              void* d_out, int out_size) {
    const float* x  = (const float*)d_in[0];
    const float* wq = (const float*)d_in[1];
    const float* bq = (const float*)d_in[2];
    const float* wk = (const float*)d_in[3];
    const float* bk = (const float*)d_in[4];
    const float* wv = (const float*)d_in[5];
    const float* bv = (const float*)d_in[6];
    float* out = (float*)d_out;

    const int SMEM = 131072;
    cudaFuncSetAttribute(qkv_gemm,  cudaFuncAttributeMaxDynamicSharedMemorySize, SMEM);
    cudaFuncSetAttribute(attn_gemm, cudaFuncAttributeMaxDynamicSharedMemorySize, SMEM);
    cudaFuncSetAttribute(out_gemm,  cudaFuncAttributeMaxDynamicSharedMemorySize, SMEM);

    split_w_kernel<<<3 * CH * CH / 256, 256>>>(wq, wk, wv);
    split_xt_kernel<<<dim3(NSP / 32, CH / 32, BATCH), dim3(32, 8)>>>(x);

    qkv_gemm<<<dim3(NSP / 128, CH / 128, BATCH * 3), 256, SMEM>>>(bq, bk, bv);

    attn_gemm<<<dim3(CH / 128, CH / 128, BATCH), 256, SMEM>>>();

    softmax_kernel<<<BATCH * CH, 256>>>();

    out_gemm<<<dim3(NSP / 128, CH / 128, BATCH), 256, SMEM>>>(x, out);
}